// round 6
// baseline (speedup 1.0000x reference)
#include <cuda_runtime.h>
#include <cstdint>

#define SDIM 128
#define S3 (SDIM*SDIM*SDIM)
#define NBATCH 2
#define NPTS 250000
#define MTOT (NBATCH*NPTS)
#define CCH 32
#define NK 27

typedef unsigned long long ull;

// ---- static device scratch ----
__device__ int   g_grid[NBATCH*S3];            // 16.8 MB voxel grid
__device__ int   g_mask[MTOT];                 // 27-bit presence mask
__device__ int   g_pin [NK*MTOT];              // in_idx for (k,p), valid iff mask bit k
__device__ float g_tmp [(size_t)MTOT*NK*CCH];  // p-major slot-dense partials
__device__ float g_buf1[MTOT*CCH];
__device__ float g_buf2[MTOT*CCH];

// ---- f32x2 helpers (sm_100+) ----
__device__ __forceinline__ ull pack2(float x, float y){
    ull r; asm("mov.b64 %0, {%1,%2};" : "=l"(r)
               : "r"(__float_as_uint(x)), "r"(__float_as_uint(y))); return r;
}
__device__ __forceinline__ void unpack2(ull v, float& x, float& y){
    unsigned lo, hi; asm("mov.b64 {%0,%1}, %2;" : "=r"(lo), "=r"(hi) : "l"(v));
    x = __uint_as_float(lo); y = __uint_as_float(hi);
}
__device__ __forceinline__ ull fma2(ull a, ull b, ull c){
    ull d; asm("fma.rn.f32x2 %0, %1, %2, %3;" : "=l"(d) : "l"(a), "l"(b), "l"(c)); return d;
}
__device__ __forceinline__ ull add2(ull a, ull b){
    ull d; asm("add.rn.f32x2 %0, %1, %2;" : "=l"(d) : "l"(a), "l"(b)); return d;
}

// ---------------------------------------------------------------
__global__ void clear_grid_kernel() {
    int i = blockIdx.x*blockDim.x + threadIdx.x;   // 4096*256 == S3*NBATCH/4
    ((int4*)g_grid)[i] = make_int4(-1,-1,-1,-1);
}

__global__ void scatter_kernel(const int* __restrict__ coords) {
    int p = blockIdx.x*blockDim.x + threadIdx.x;
    if (p >= MTOT) return;
    int cx = coords[3*p], cy = coords[3*p+1], cz = coords[3*p+2];
    g_grid[(p/NPTS)*S3 + (cx*SDIM + cy)*SDIM + cz] = p;
}

// atomic-free build: direct per-point writes of mask + per-k in-indices
__global__ void build_kernel(const int* __restrict__ coords) {
    int p = blockIdx.x*blockDim.x + threadIdx.x;
    if (p >= MTOT) return;
    int cx = coords[3*p], cy = coords[3*p+1], cz = coords[3*p+2];
    const int* gb = g_grid + (p/NPTS)*S3;
    unsigned m = 0;
    #pragma unroll
    for (int dx = 0; dx < 3; dx++) {
        int nx = cx + dx - 1;
        if ((unsigned)nx >= SDIM) continue;
        #pragma unroll
        for (int dy = 0; dy < 3; dy++) {
            int ny = cy + dy - 1;
            if ((unsigned)ny >= SDIM) continue;
            int base = (nx*SDIM + ny)*SDIM;
            #pragma unroll
            for (int dz = 0; dz < 3; dz++) {       // z innermost: 3 probes share a sector
                int nz = cz + dz - 1;
                if ((unsigned)nz >= SDIM) continue;
                int idx = gb[base + nz];
                if (idx >= 0) {
                    int k = (dx*3 + dy)*3 + dz;
                    m |= (1u << k);
                    g_pin[k*MTOT + p] = idx;
                }
            }
        }
    }
    g_mask[p] = (int)m;
}

// ---------------------------------------------------------------
// k-major conv: W[k] dup-packed in 64 regs; warp scans 32-point groups,
// compacts actives to smem, processes 4 pairs/step (1 LDG.128/lane = 4 rows),
// 16 FFMA2 per pair, 1-step row prefetch, double-buffered staging.
#define CV_THREADS 256
#define CV_WARPS   8
#define CV_CHUNK   256     // points per warp

__global__ void __launch_bounds__(CV_THREADS, 2)
conv_k_kernel(const float* __restrict__ fext_in, const float* __restrict__ Wg,
              int in_mode)
{
    __shared__ int sIdx[CV_WARPS][32];
    __shared__ int sDst[CV_WARPS][32];
    __shared__ __align__(16) float2 sAB[CV_WARPS][2][CCH];
    __shared__ __align__(16) float2 sCD[CV_WARPS][2][CCH];

    const int k    = blockIdx.y;
    const int warp = threadIdx.x >> 5, lane = threadIdx.x & 31;
    const int q    = lane >> 3,        ql   = lane & 7;       // quarter, quarter-lane
    const float* fin = (in_mode == 0) ? fext_in : (in_mode == 1 ? g_buf1 : g_buf2);

    // W[k] column c=lane, dup-packed for f32x2
    ull wd[CCH];
    #pragma unroll
    for (int j = 0; j < CCH; j++) {
        float w = Wg[k*CCH*CCH + j*CCH + lane];
        wd[j] = pack2(w, w);
    }

    const int      kbase = k*MTOT;
    const unsigned kb    = 1u << k, kml = kb - 1u;
    unsigned lt; asm("mov.u32 %0, %%lanemask_lt;" : "=r"(lt));

    const int wbase = (blockIdx.x*CV_WARPS + warp)*CV_CHUNK;

    for (int g = 0; g < CV_CHUNK/32; g++) {
        const int p = wbase + g*32 + lane;
        const int mv = (p < MTOT) ? g_mask[p] : 0;
        const unsigned act = __ballot_sync(0xFFFFFFFFu, mv & kb);
        if (!act) continue;
        const int nact = __popc(act);

        if (mv & kb) {                                   // compact actives to smem
            int pos = __popc(act & lt);
            sIdx[warp][pos] = g_pin[kbase + p];          // coalesced predicated
            sDst[warp][pos] = p*NK + __popc((unsigned)mv & kml);   // slot-dense row
        }
        __syncwarp();

        // prologue: gather rows for pairs 0..3 (quarter q -> pair q, ql -> float4 seg)
        float4 cur;
        { int ip = q; if (ip >= nact) ip = nact - 1;
          cur = *(const float4*)(fin + (size_t)sIdx[warp][ip]*CCH + ql*4); }

        for (int e = 0; e < nact; e += 4) {
            // prefetch rows for pairs e+4..e+7
            float4 nxt = cur;
            if (e + 4 < nact) {
                int ip = e + 4 + q; if (ip >= nact) ip = nact - 1;
                nxt = *(const float4*)(fin + (size_t)sIdx[warp][ip]*CCH + ql*4);
            }

            // stage interleaved (fA[j],fB[j]) / (fC[j],fD[j]) — double-buffered
            float2* ab = sAB[warp][(e >> 2) & 1];
            float2* cd = sCD[warp][(e >> 2) & 1];
            if      (q == 0) { ab[4*ql+0].x = cur.x; ab[4*ql+1].x = cur.y; ab[4*ql+2].x = cur.z; ab[4*ql+3].x = cur.w; }
            else if (q == 1) { ab[4*ql+0].y = cur.x; ab[4*ql+1].y = cur.y; ab[4*ql+2].y = cur.z; ab[4*ql+3].y = cur.w; }
            else if (q == 2) { cd[4*ql+0].x = cur.x; cd[4*ql+1].x = cur.y; cd[4*ql+2].x = cur.z; cd[4*ql+3].x = cur.w; }
            else             { cd[4*ql+0].y = cur.x; cd[4*ql+1].y = cur.y; cd[4*ql+2].y = cur.z; cd[4*ql+3].y = cur.w; }
            __syncwarp();

            ull aAB0 = 0, aAB1 = 0, aCD0 = 0, aCD1 = 0;
            #pragma unroll
            for (int t = 0; t < 16; t++) {
                ulonglong2 vab = *(const ulonglong2*)&ab[2*t];   // broadcast LDS.128: j=2t,2t+1
                aAB0 = fma2(vab.x, wd[2*t],   aAB0);
                aAB1 = fma2(vab.y, wd[2*t+1], aAB1);
                ulonglong2 vcd = *(const ulonglong2*)&cd[2*t];
                aCD0 = fma2(vcd.x, wd[2*t],   aCD0);
                aCD1 = fma2(vcd.y, wd[2*t+1], aCD1);
            }
            float fa, fb, fc, fd;
            unpack2(add2(aAB0, aAB1), fa, fb);
            unpack2(add2(aCD0, aCD1), fc, fd);

            g_tmp[(size_t)sDst[warp][e]*CCH + lane] = fa;                      // e < nact always
            if (e+1 < nact) g_tmp[(size_t)sDst[warp][e+1]*CCH + lane] = fb;
            if (e+2 < nact) g_tmp[(size_t)sDst[warp][e+2]*CCH + lane] = fc;
            if (e+3 < nact) g_tmp[(size_t)sDst[warp][e+3]*CCH + lane] = fd;

            cur = nxt;
        }
        __syncwarp();   // protect sIdx/sDst before next group's writes
    }
}

// ---------------------------------------------------------------
// Phase 2: per-point sum over slot-dense rows + fused ReLU (BW-bound).
template<bool RELU>
__global__ void __launch_bounds__(256)
reduce_kernel(float* __restrict__ fext_out, int out_mode)
{
    const int p = blockIdx.x*8 + (threadIdx.x >> 5);
    if (p >= MTOT) return;
    const int lane = threadIdx.x & 31;
    float* fout = (out_mode == 0) ? fext_out : (out_mode == 1 ? g_buf1 : g_buf2);

    const int c = __popc((unsigned)g_mask[p]);
    const float* t = g_tmp + (size_t)p*NK*CCH + lane;
    float a0 = 0.f, a1 = 0.f, a2 = 0.f, a3 = 0.f;
    int s = 0;
    for (; s + 4 <= c; s += 4) {
        a0 += t[(s  )*CCH]; a1 += t[(s+1)*CCH];
        a2 += t[(s+2)*CCH]; a3 += t[(s+3)*CCH];
    }
    for (; s < c; s++) a0 += t[s*CCH];
    float r = (a0 + a1) + (a2 + a3);
    if (RELU) r = fmaxf(r, 0.f);
    fout[(size_t)p*CCH + lane] = r;
}

// ---------------------------------------------------------------
extern "C" void kernel_launch(void* const* d_in, const int* in_sizes, int n_in,
                              void* d_out, int out_size)
{
    const float* features = (const float*)d_in[0];
    const int*   coords   = (const int*)  d_in[1];
    const float* W1 = (const float*)d_in[n_in-3];
    const float* W2 = (const float*)d_in[n_in-2];
    const float* W3 = (const float*)d_in[n_in-1];
    float* out = (float*)d_out;

    clear_grid_kernel<<<(NBATCH*S3/4)/256, 256>>>();
    scatter_kernel  <<<(MTOT+255)/256, 256>>>(coords);
    build_kernel    <<<(MTOT+255)/256, 256>>>(coords);

    dim3 g1((MTOT + CV_WARPS*CV_CHUNK - 1)/(CV_WARPS*CV_CHUNK), NK);  // (245, 27)
    const int g2 = (MTOT + 7)/8;

    conv_k_kernel<<<g1, CV_THREADS>>>(features, W1, 0);
    reduce_kernel<true ><<<g2, 256>>>(nullptr, 1);

    conv_k_kernel<<<g1, CV_THREADS>>>(nullptr, W2, 1);
    reduce_kernel<true ><<<g2, 256>>>(nullptr, 2);

    conv_k_kernel<<<g1, CV_THREADS>>>(nullptr, W3, 2);
    reduce_kernel<false><<<g2, 256>>>(out, 0);
}